// round 16
// baseline (speedup 1.0000x reference)
#include <cuda_runtime.h>

#define NB    8
#define NH    16
#define HDIM  64
#define NDIMS 1024
#define CTXL  4096

// Scratch (__device__ globals: allocation-free rule)
__device__ __align__(16) float g_q [128 * 1024];
__device__ __align__(16) float g_k [128 * 1024];
__device__ __align__(16) float g_v [128 * 1024];
__device__ __align__(16) float g_A1[128 * 1024];
__device__ __align__(16) float g_A2[128 * 1024];
__device__ float g_diffpart[128];

// ---------------------------------------------------------------------------
// tf32 helpers
// ---------------------------------------------------------------------------
__device__ __forceinline__ unsigned f2tf(float f) {
    unsigned r;
    asm("cvt.rna.tf32.f32 %0, %1;" : "=r"(r) : "f"(f));
    return r;
}
__device__ __forceinline__ void mma_tf32(float* c, unsigned a0, unsigned a1,
                                         unsigned a2, unsigned a3,
                                         unsigned b0, unsigned b1) {
    asm("mma.sync.aligned.m16n8k8.row.col.f32.tf32.tf32.f32 "
        "{%0,%1,%2,%3},{%4,%5,%6,%7},{%8,%9},{%0,%1,%2,%3};"
        : "+f"(c[0]), "+f"(c[1]), "+f"(c[2]), "+f"(c[3])
        : "r"(a0), "r"(a1), "r"(a2), "r"(a3), "r"(b0), "r"(b1));
}

// ---------------------------------------------------------------------------
// Kernel 1: fill — proven 21.8us shape. 32768 blocks x 256 threads, one
// float4/thread, fully coalesced. Writes ob everywhere; proj atomicAdds onto
// the s<16 rows afterwards. Runs on a forked stream, parallel to qkv+attn.
// ---------------------------------------------------------------------------
__global__ void __launch_bounds__(256) fill_kernel(float4* __restrict__ out,
                                                   const float4* __restrict__ ob4) {
    unsigned i = blockIdx.x * 256u + threadIdx.x;
    out[i] = ob4[threadIdx.x];   // element col = (4*i)&1023 -> float4 col = tid
}

// ---------------------------------------------------------------------------
// Kernel 2: fused LN + q/k/v tf32 GEMM. 192 blocks (mat, 32x64 tile),
// K-tile 64 with register prefetch.
// ---------------------------------------------------------------------------
__global__ void __launch_bounds__(256) qkv_kernel(
    const float* __restrict__ x,
    const float* __restrict__ qw, const float* __restrict__ qb,
    const float* __restrict__ kw,
    const float* __restrict__ vw, const float* __restrict__ vb,
    const float* __restrict__ lna, const float* __restrict__ lnb)
{
    const int t = threadIdx.x;
    const int bid = blockIdx.x;
    const int mat = bid >> 6;
    const int sub = bid & 63;
    const int r0 = (sub >> 4) * 32, c0 = (sub & 15) * 64;
    const float* W    = (mat == 0) ? qw : (mat == 1) ? kw : vw;
    const float* lnw  = (mat == 0) ? lna : lnb;
    const float* bias = (mat == 0) ? qb : (mat == 2) ? vb : (const float*)0;
    float* OUT        = (mat == 0) ? g_q : (mat == 1) ? g_k : g_v;

    __shared__ float As[32][68];
    __shared__ float Ws[64][68];
    __shared__ float m_s[32], r_s[32];

    // ---- LN stats for this tile's 32 rows (8 threads per row) ----
    const int lr = t >> 3, sg = t & 7;
    const int grow = r0 + lr;
    const float* xrow = x + ((size_t)(grow >> 4) * CTXL + (grow & 15)) * NDIMS;
    {
        float sum = 0.f, sq = 0.f;
        const float4* x4 = (const float4*)xrow;
        for (int j = sg; j < 256; j += 8) {
            float4 vv = x4[j];
            sum += vv.x + vv.y + vv.z + vv.w;
            sq  += vv.x*vv.x + vv.y*vv.y + vv.z*vv.z + vv.w*vv.w;
        }
        #pragma unroll
        for (int o = 4; o; o >>= 1) {
            sum += __shfl_xor_sync(0xffffffffu, sum, o);
            sq  += __shfl_xor_sync(0xffffffffu, sq,  o);
        }
        if (sg == 0) {
            float m = sum * (1.f / 1024.f);
            float var = sq * (1.f / 1024.f) - m * m;
            m_s[lr] = m; r_s[lr] = rsqrtf(var + 1e-5f);
        }
    }
    __syncthreads();
    const float mm = m_s[lr], rs = r_s[lr];

    // ---- GEMM ----
    const int w = t >> 5, l = t & 31;
    const int mr  = (w >> 2) * 16;
    const int nc_ = (w & 3) * 16;
    const int g   = l >> 2, tig = l & 3;
    const int lk8 = sg * 8;

    const float* xp  = xrow + lk8;
    const float* Wp0 = W + (size_t)(c0 + lr) * 1024 + lk8;
    const float* Wp1 = W + (size_t)(c0 + 32 + lr) * 1024 + lk8;
    const float* lp  = lnw + lk8;

    float4 px0 = *(const float4*)xp,  px1 = *(const float4*)(xp + 4);
    float4 pw0 = *(const float4*)Wp0, pw1 = *(const float4*)(Wp0 + 4);
    float4 pw2 = *(const float4*)Wp1, pw3 = *(const float4*)(Wp1 + 4);

    float acc[2][4] = {{0,0,0,0},{0,0,0,0}};

    for (int k0 = 0; k0 < 1024; k0 += 64) {
        __syncthreads();
        {
            float4 pl0 = *(const float4*)(lp + k0);
            float4 pl1 = *(const float4*)(lp + k0 + 4);
            float4 a0, a1;
            a0.x = (px0.x - mm) * rs * pl0.x; a0.y = (px0.y - mm) * rs * pl0.y;
            a0.z = (px0.z - mm) * rs * pl0.z; a0.w = (px0.w - mm) * rs * pl0.w;
            a1.x = (px1.x - mm) * rs * pl1.x; a1.y = (px1.y - mm) * rs * pl1.y;
            a1.z = (px1.z - mm) * rs * pl1.z; a1.w = (px1.w - mm) * rs * pl1.w;
            *(float4*)&As[lr][lk8]     = a0;
            *(float4*)&As[lr][lk8 + 4] = a1;
            *(float4*)&Ws[lr][lk8]          = pw0; *(float4*)&Ws[lr][lk8 + 4]      = pw1;
            *(float4*)&Ws[lr + 32][lk8]     = pw2; *(float4*)&Ws[lr + 32][lk8 + 4] = pw3;
        }
        __syncthreads();
        if (k0 + 64 < 1024) {
            px0 = *(const float4*)(xp  + k0 + 64); px1 = *(const float4*)(xp  + k0 + 68);
            pw0 = *(const float4*)(Wp0 + k0 + 64); pw1 = *(const float4*)(Wp0 + k0 + 68);
            pw2 = *(const float4*)(Wp1 + k0 + 64); pw3 = *(const float4*)(Wp1 + k0 + 68);
        }
        #pragma unroll
        for (int ks = 0; ks < 8; ks++) {
            const int kb = ks * 8;
            unsigned a0 = f2tf(As[mr + g][kb + tig]);
            unsigned a1 = f2tf(As[mr + g + 8][kb + tig]);
            unsigned a2 = f2tf(As[mr + g][kb + tig + 4]);
            unsigned a3 = f2tf(As[mr + g + 8][kb + tig + 4]);
            #pragma unroll
            for (int j = 0; j < 2; j++) {
                unsigned b0 = f2tf(Ws[nc_ + j * 8 + g][kb + tig]);
                unsigned b1 = f2tf(Ws[nc_ + j * 8 + g][kb + tig + 4]);
                mma_tf32(acc[j], a0, a1, a2, a3, b0, b1);
            }
        }
    }
    const int row0 = r0 + mr + g, row1 = row0 + 8;
    #pragma unroll
    for (int j = 0; j < 2; j++) {
        const int colb = c0 + nc_ + j * 8 + 2 * tig;
        float b0v = 0.f, b1v = 0.f;
        if (bias) { b0v = bias[colb]; b1v = bias[colb + 1]; }
        OUT[(size_t)row0 * 1024 + colb]     = acc[j][0] + b0v;
        OUT[(size_t)row0 * 1024 + colb + 1] = acc[j][1] + b1v;
        OUT[(size_t)row1 * 1024 + colb]     = acc[j][2] + b0v;
        OUT[(size_t)row1 * 1024 + colb + 1] = acc[j][3] + b1v;
    }
}

// ---------------------------------------------------------------------------
// Kernel 3: attention per (b,h), 128 blocks, sync-free iteration loop.
// Dynamic smem 54.2KB (qn aliases dead kt).
// ---------------------------------------------------------------------------
__global__ void __launch_bounds__(256) attn_kernel(
    const float* __restrict__ lnc, const float* __restrict__ lnd,
    const float* __restrict__ lqw, const float* __restrict__ lqb,
    const float* __restrict__ lkw, const float* __restrict__ lkb,
    const float* __restrict__ lvw, const float* __restrict__ lvb)
{
    extern __shared__ float sm[];
    const int t = threadIdx.x;
    const int aidx = blockIdx.x;
    const int b = aidx >> 4, h = aidx & 15;

    float (*w1)[65] = (float(*)[65])sm;          // wk, later wq (64x65)
    float (*w2)[65] = w1 + 64;                   // wv
    float (*kt)[65] = w2 + 64;                   // k tile; later aliased as qn
    float (*vt)[65] = kt + 16;
    float (*kn)[65] = vt + 16;
    float (*vi)[65] = kn + 16;
    float (*qc)[65] = vi + 16;
    float (*qn)[65] = kt;                        // ALIAS: kt dead after kn/vi
    float* rm  = (float*)(qc + 16);
    float* rr  = rm + 16;

    const int w = t >> 5, lane = t & 31;

    // stage wk->w1, wv->w2
    {
        const int rw = t >> 4, col = (t & 15) * 4;
        #pragma unroll
        for (int p = 0; p < 4; p++) {
            int row = p * 16 + rw;
            float4 c = *(const float4*)(lkw + row * 64 + col);
            w1[row][col] = c.x; w1[row][col+1] = c.y; w1[row][col+2] = c.z; w1[row][col+3] = c.w;
            float4 e = *(const float4*)(lvw + row * 64 + col);
            w2[row][col] = e.x; w2[row][col+1] = e.y; w2[row][col+2] = e.z; w2[row][col+3] = e.w;
        }
    }
    const int d = t & 63, s0 = t >> 6;
    const size_t base = (size_t)(b * 16) * 1024 + h * 64;
    #pragma unroll
    for (int r = 0; r < 4; r++) {
        int s = s0 + 4 * r;
        qc[s][d] = g_q[base + (size_t)s * 1024 + d];
        kt[s][d] = g_k[base + (size_t)s * 1024 + d];
        vt[s][d] = g_v[base + (size_t)s * 1024 + d];
    }
    __syncthreads();

    // kn_pre = k @ lkw.T + lkb, vi = v @ lvw.T + lvb
    {
        float akn[4], avi[4];
        const float bk = lkb[d], bv = lvb[d];
        #pragma unroll
        for (int r = 0; r < 4; r++) { akn[r] = bk; avi[r] = bv; }
        for (int e = 0; e < 64; e++) {
            float wke = w1[d][e], wve = w2[d][e];
            #pragma unroll
            for (int r = 0; r < 4; r++) {
                int s = s0 + 4 * r;
                akn[r] += kt[s][e] * wke;
                avi[r] += vt[s][e] * wve;
            }
        }
        #pragma unroll
        for (int r = 0; r < 4; r++) { int s = s0 + 4 * r; kn[s][d] = akn[r]; vi[s][d] = avi[r]; }
    }
    __syncthreads();                             // kt fully dead after this
    {   // LN over 64-dim kn rows
        const int s = t >> 4, l16 = t & 15;
        float v0 = kn[s][l16], v1 = kn[s][l16+16], v2 = kn[s][l16+32], v3 = kn[s][l16+48];
        float sum = v0+v1+v2+v3, sq = v0*v0+v1*v1+v2*v2+v3*v3;
        #pragma unroll
        for (int o = 8; o; o >>= 1) {
            sum += __shfl_xor_sync(0xffffffffu, sum, o);
            sq  += __shfl_xor_sync(0xffffffffu, sq,  o);
        }
        if (l16 == 0) {
            float m = sum * (1.f/64.f), var = sq * (1.f/64.f) - m*m;
            rm[s] = m; rr[s] = rsqrtf(var + 1e-5f);
        }
    }
    __syncthreads();
    {
        const float lndd = lnd[d];
        #pragma unroll
        for (int r = 0; r < 4; r++) {
            int s = s0 + 4 * r;
            kn[s][d] = (kn[s][d] - rm[s]) * rr[s] * lndd;
        }
    }
    __syncthreads();
    // restage wq into w1 (wk no longer needed)
    {
        const int rw = t >> 4, col = (t & 15) * 4;
        #pragma unroll
        for (int p = 0; p < 4; p++) {
            int row = p * 16 + rw;
            float4 a = *(const float4*)(lqw + row * 64 + col);
            w1[row][col] = a.x; w1[row][col+1] = a.y; w1[row][col+2] = a.z; w1[row][col+3] = a.w;
        }
    }
    __syncthreads();

    // ---- sync-free iteration loop: warp w owns rows sA=2w, sB=2w+1 ----
    const int d0 = lane, d1 = lane + 32;
    const int sA = 2 * w, sB = sA + 1;
    const float lqb0 = lqb[d0], lqb1 = lqb[d1];
    const float lnc0 = lnc[d0], lnc1 = lnc[d1];
    const size_t baseA = base + (size_t)sA * 1024;
    const size_t baseB = base + (size_t)sB * 1024;

    float diffacc = 0.f;
    float ipA0 = 0.f, ipA1 = 0.f, ipB0 = 0.f, ipB1 = 0.f;

    #pragma unroll
    for (int it = 0; it < 3; it++) {
        float aA0 = lqb0, aA1 = lqb1, aB0 = lqb0, aB1 = lqb1;
        #pragma unroll 16
        for (int e = 0; e < 64; e++) {
            float ca = qc[sA][e], cb = qc[sB][e];
            float w0 = w1[d0][e], wv1 = w1[d1][e];
            aA0 += ca * w0; aA1 += ca * wv1;
            aB0 += cb * w0; aB1 += cb * wv1;
        }
        float sumA = aA0 + aA1, sqA = aA0*aA0 + aA1*aA1;
        float sumB = aB0 + aB1, sqB = aB0*aB0 + aB1*aB1;
        #pragma unroll
        for (int o = 16; o; o >>= 1) {
            sumA += __shfl_xor_sync(0xffffffffu, sumA, o);
            sqA  += __shfl_xor_sync(0xffffffffu, sqA,  o);
            sumB += __shfl_xor_sync(0xffffffffu, sumB, o);
            sqB  += __shfl_xor_sync(0xffffffffu, sqB,  o);
        }
        float mA = sumA * (1.f/64.f), rA = rsqrtf(sqA * (1.f/64.f) - mA*mA + 1e-5f);
        float mB = sumB * (1.f/64.f), rB = rsqrtf(sqB * (1.f/64.f) - mB*mB + 1e-5f);
        qn[sA][d0] = (aA0 - mA) * rA * lnc0; qn[sA][d1] = (aA1 - mA) * rA * lnc1;
        qn[sB][d0] = (aB0 - mB) * rB * lnc0; qn[sB][d1] = (aB1 - mB) * rB * lnc1;
        __syncwarp();

        const int srow = (lane < 16) ? sA : sB;
        const int u = lane & 15;
        float lg = 0.f;
        #pragma unroll 16
        for (int e = 0; e < 64; e++) lg += qn[srow][e] * kn[u][e];
        lg *= 0.125f;
        float mx = lg;
        #pragma unroll
        for (int o = 8; o; o >>= 1) mx = fmaxf(mx, __shfl_xor_sync(0xffffffffu, mx, o));
        float ex = expf(lg - mx);
        float se = ex;
        #pragma unroll
        for (int o = 8; o; o >>= 1) se += __shfl_xor_sync(0xffffffffu, se, o);
        float p = ex / se;

        float oA0 = 0.f, oA1 = 0.f, oB0 = 0.f, oB1 = 0.f;
        #pragma unroll
        for (int uu = 0; uu < 16; uu++) {
            float pA = __shfl_sync(0xffffffffu, p, uu);
            float pB = __shfl_sync(0xffffffffu, p, uu + 16);
            float v0 = vi[uu][d0], vvv = vi[uu][d1];
            oA0 += pA * v0; oA1 += pA * vvv;
            oB0 += pB * v0; oB1 += pB * vvv;
        }

        if (it == 0) {
            ipA0 = oA0; ipA1 = oA1; ipB0 = oB0; ipB1 = oB1;
            qc[sA][d0] += oA0; qc[sA][d1] += oA1;
            qc[sB][d0] += oB0; qc[sB][d1] += oB1;
        } else if (it == 1) {
            diffacc += fabsf(oA0 - ipA0) + fabsf(oA1 - ipA1)
                     + fabsf(oB0 - ipB0) + fabsf(oB1 - ipB1);
            qc[sA][d0] += oA0; qc[sA][d1] += oA1;
            qc[sB][d0] += oB0; qc[sB][d1] += oB1;
            g_A1[baseA + d0] = oA0; g_A1[baseA + d1] = oA1;
            g_A1[baseB + d0] = oB0; g_A1[baseB + d1] = oB1;
        } else {
            g_A2[baseA + d0] = oA0; g_A2[baseA + d1] = oA1;
            g_A2[baseB + d0] = oB0; g_A2[baseB + d1] = oB1;
        }
        __syncwarp();
    }

    // block reduce diff -> g_diffpart[aidx] (consumed by proj next kernel)
    #pragma unroll
    for (int o = 16; o; o >>= 1) diffacc += __shfl_xor_sync(0xffffffffu, diffacc, o);
    __shared__ float red[8];
    if (lane == 0) red[w] = diffacc;
    __syncthreads();
    if (t == 0) {
        float v = 0.f;
        #pragma unroll
        for (int i = 0; i < 8; i++) v += red[i];
        g_diffpart[aidx] = v;
    }
}

// ---------------------------------------------------------------------------
// Kernel 4: output projection, split-K x4 tf32 GEMM (256 blocks), atomicAdd
// onto the ob-prefilled s<16 rows. Waits on BOTH branches (fill + attn).
// ---------------------------------------------------------------------------
__global__ void __launch_bounds__(256) proj_kernel(
    const float* __restrict__ ow, float* __restrict__ out)
{
    const int t = threadIdx.x;
    const int bid = blockIdx.x;
    const int ksl = bid >> 6;                  // k-slice 0..3
    const int sub = bid & 63;
    const int r0 = (sub >> 4) * 32;
    const int c0 = (sub & 15) * 64;
    const int kbase = ksl * 256;

    __shared__ float As[32][68];
    __shared__ float Ws[64][68];
    __shared__ float s_total;

    // deterministic diff reduction (identical order in every block)
    if (t < 32) {
        float v = 0.f;
        #pragma unroll
        for (int j = 0; j < 4; j++) v += g_diffpart[t + j * 32];
        #pragma unroll
        for (int o = 16; o; o >>= 1) v += __shfl_xor_sync(0xffffffffu, v, o);
        if (t == 0) s_total = v;
    }
    __syncthreads();
    const float diff = s_total * (1.0f / 33554432.0f);
    const float* IN = (diff < (0.01f + 0.1f * diff)) ? g_A1 : g_A2;

    const int w = t >> 5, l = t & 31;
    const int mr  = (w >> 2) * 16;
    const int nc_ = (w & 3) * 16;
    const int g   = l >> 2, tig = l & 3;
    const int lr  = t >> 3, lk8 = (t & 7) * 8;

    float acc[2][4] = {{0,0,0,0},{0,0,0,0}};

    const float* Ap  = IN + (size_t)(r0 + lr) * 1024 + kbase + lk8;
    const float* Wp0 = ow + (size_t)(c0 + lr) * 1024 + kbase + lk8;
    const float* Wp1 = ow + (size_t)(c0 + 32 + lr) * 1024 + kbase + lk8;
    float4 pa0 = *(const float4*)Ap,  pa1 = *(const float4*)(Ap + 4);
    float4 pw0 = *(const float4*)Wp0, pw1 = *(const float4*)(Wp0 + 4);
    float4 pw2 = *(const float4*)Wp1, pw3 = *(const float4*)(Wp1 + 4);

    for (int k0 = 0; k0 < 256; k0 += 64) {
        __syncthreads();
        *(float4*)&As[lr][lk8]          = pa0; *(float4*)&As[lr][lk8 + 4]      = pa1;
        *(float4*)&Ws[lr][lk8]          = pw0; *(float4*)&Ws[lr][lk8 + 4]      = pw1;
        *(float4*)&Ws[lr + 32][lk8]     = pw2; *(float4*)&Ws[lr + 32][lk8 + 4] = pw3;
        __syncthreads();
        if (k0 + 64 < 256) {
            pa0 = *(const float4*)(Ap  + k0 + 64); pa1 = *(const float4*)(Ap  + k0 + 68);
            pw0 = *(const float4*)(Wp0 + k0 + 64); pw1 = *(const float4*)(Wp0 + k0 + 68);
            pw2 = *(const float4*)(Wp1 + k0 + 64); pw3 = *(const float4*)(Wp1 + k0 + 68);
        }
        #pragma unroll
        for (int ks = 0; ks < 8; ks++) {
            const int kb = ks * 8;
            unsigned a0 = f2tf(As[mr + g][kb + tig]);
            unsigned a1 = f2tf(As[mr + g + 8][kb + tig]);
            unsigned a2 = f2tf(As[mr + g][kb + tig + 4]);
            unsigned a3 = f2tf(As[mr + g + 8][kb + tig + 4]);
            #pragma unroll
            for (int j = 0; j < 2; j++) {
                unsigned b0 = f2tf(Ws[nc_ + j * 8 + g][kb + tig]);
                unsigned b1 = f2tf(Ws[nc_ + j * 8 + g][kb + tig + 4]);
                mma_tf32(acc[j], a0, a1, a2, a3, b0, b1);
            }
        }
    }
    const int row0 = r0 + mr + g, row1 = row0 + 8;
    const size_t o0 = ((size_t)(row0 >> 4) * CTXL + (row0 & 15)) * 1024;
    const size_t o1 = ((size_t)(row1 >> 4) * CTXL + (row1 & 15)) * 1024;
    #pragma unroll
    for (int j = 0; j < 2; j++) {
        const int colb = c0 + nc_ + j * 8 + 2 * tig;
        atomicAdd(&out[o0 + colb],     acc[j][0]);
        atomicAdd(&out[o0 + colb + 1], acc[j][1]);
        atomicAdd(&out[o1 + colb],     acc[j][2]);
        atomicAdd(&out[o1 + colb + 1], acc[j][3]);
    }
}

// ---------------------------------------------------------------------------
// Launch: fork the fill onto a second stream (graph branch), run qkv+attn on
// the main captured stream concurrently, join before proj.
// ---------------------------------------------------------------------------
extern "C" void kernel_launch(void* const* d_in, const int* in_sizes, int n_in,
                              void* d_out, int out_size) {
    const float* x   = (const float*)d_in[0];
    const float* qw  = (const float*)d_in[1];
    const float* qb  = (const float*)d_in[2];
    const float* kw  = (const float*)d_in[3];
    const float* vw  = (const float*)d_in[4];
    const float* vb  = (const float*)d_in[5];
    const float* ow  = (const float*)d_in[6];
    const float* ob  = (const float*)d_in[7];
    const float* lna = (const float*)d_in[8];
    const float* lnb = (const float*)d_in[9];
    const float* lnc = (const float*)d_in[10];
    const float* lnd = (const float*)d_in[11];
    const float* lqw = (const float*)d_in[12];
    const float* lqb = (const float*)d_in[13];
    const float* lkw = (const float*)d_in[14];
    const float* lkb = (const float*)d_in[15];
    const float* lvw = (const float*)d_in[16];
    const float* lvb = (const float*)d_in[17];
    float* out = (float*)d_out;

    // One-time host resources (streams/events are not device memory).
    static cudaStream_t s_fill = nullptr;
    static cudaEvent_t  ev_fork = nullptr, ev_join = nullptr;
    if (s_fill == nullptr) {
        cudaStreamCreateWithFlags(&s_fill, cudaStreamNonBlocking);
        cudaEventCreateWithFlags(&ev_fork, cudaEventDisableTiming);
        cudaEventCreateWithFlags(&ev_join, cudaEventDisableTiming);
        const int attn_smem = (2 * 64 * 65 + 5 * 16 * 65 + 40) * 4;
        cudaFuncSetAttribute(attn_kernel,
                             cudaFuncAttributeMaxDynamicSharedMemorySize,
                             attn_smem);
    }
    const int attn_smem = (2 * 64 * 65 + 5 * 16 * 65 + 40) * 4;

    // Fork: s_fill joins the capture via the event dependency.
    cudaEventRecord(ev_fork, 0);
    cudaStreamWaitEvent(s_fill, ev_fork, 0);
    fill_kernel<<<32768, 256, 0, s_fill>>>((float4*)out, (const float4*)ob);
    cudaEventRecord(ev_join, s_fill);

    // Main branch: compute chain (touches only __device__ scratch).
    qkv_kernel<<<192, 256>>>(x, qw, qb, kw, vw, vb, lna, lnb);
    attn_kernel<<<128, 256, attn_smem>>>(lnc, lnd, lqw, lqb, lkw, lkb, lvw, lvb);

    // Join: proj needs both the filled output rows and the attn results.
    cudaStreamWaitEvent(0, ev_join, 0);
    proj_kernel<<<256, 256>>>(ow, out);
}

// round 17
// speedup vs baseline: 2.2689x; 2.2689x over previous
#include <cuda_runtime.h>

#define NB    8
#define NH    16
#define HDIM  64
#define NDIMS 1024
#define CTXL  4096

// Scratch (__device__ globals: allocation-free rule)
__device__ __align__(16) float g_q [128 * 1024];
__device__ __align__(16) float g_k [128 * 1024];
__device__ __align__(16) float g_v [128 * 1024];
__device__ __align__(16) float g_A1[128 * 1024];
__device__ __align__(16) float g_A2[128 * 1024];
__device__ float g_diffpart[128];

// ---------------------------------------------------------------------------
// tf32 helpers
// ---------------------------------------------------------------------------
__device__ __forceinline__ unsigned f2tf(float f) {
    unsigned r;
    asm("cvt.rna.tf32.f32 %0, %1;" : "=r"(r) : "f"(f));
    return r;
}
__device__ __forceinline__ void mma_tf32(float* c, unsigned a0, unsigned a1,
                                         unsigned a2, unsigned a3,
                                         unsigned b0, unsigned b1) {
    asm("mma.sync.aligned.m16n8k8.row.col.f32.tf32.tf32.f32 "
        "{%0,%1,%2,%3},{%4,%5,%6,%7},{%8,%9},{%0,%1,%2,%3};"
        : "+f"(c[0]), "+f"(c[1]), "+f"(c[2]), "+f"(c[3])
        : "r"(a0), "r"(a1), "r"(a2), "r"(a3), "r"(b0), "r"(b1));
}

// ---------------------------------------------------------------------------
// Kernel A: fused LN + q/k/v tf32 GEMM (bids 0..191) + one-shot churn fill.
// Fill blocks (bids 192..16639): one float4 per thread, then retire.
//   - 16384 blocks cover out4[0, 4194304)  (includes b0..b3 active rows)
//   - 64 blocks cover the b4..b7 active (s<16) slices
// ---------------------------------------------------------------------------
__global__ void __launch_bounds__(256) qkv_kernel(
    const float* __restrict__ x,
    const float* __restrict__ qw, const float* __restrict__ qb,
    const float* __restrict__ kw,
    const float* __restrict__ vw, const float* __restrict__ vb,
    const float* __restrict__ lna, const float* __restrict__ lnb,
    float4* __restrict__ out4, const float4* __restrict__ ob4)
{
    const int t = threadIdx.x;
    const int bid = blockIdx.x;

    if (bid >= 192) {
        const int f = bid - 192;
        unsigned i;
        if (f < 16384) {
            i = (unsigned)f * 256u + t;                      // [0, 4194304)
        } else {
            const int e = f - 16384;                         // 0..63
            const unsigned batch = 4u + (unsigned)(e >> 4);  // b4..b7
            i = batch * 1048576u + (unsigned)(e & 15) * 256u + t;  // active slice
        }
        out4[i] = ob4[t];         // i mod 256 == t -> column matches
        return;
    }

    const int mat = bid >> 6;
    const int sub = bid & 63;
    const int r0 = (sub >> 4) * 32, c0 = (sub & 15) * 64;
    const float* W    = (mat == 0) ? qw : (mat == 1) ? kw : vw;
    const float* lnw  = (mat == 0) ? lna : lnb;
    const float* bias = (mat == 0) ? qb : (mat == 2) ? vb : (const float*)0;
    float* OUT        = (mat == 0) ? g_q : (mat == 1) ? g_k : g_v;

    __shared__ float As[32][68];
    __shared__ float Ws[64][68];
    __shared__ float m_s[32], r_s[32];

    // ---- LN stats for this tile's 32 rows (8 threads per row) ----
    const int lr = t >> 3, sg = t & 7;
    const int grow = r0 + lr;
    const float* xrow = x + ((size_t)(grow >> 4) * CTXL + (grow & 15)) * NDIMS;
    {
        float sum = 0.f, sq = 0.f;
        const float4* x4 = (const float4*)xrow;
        for (int j = sg; j < 256; j += 8) {
            float4 vv = x4[j];
            sum += vv.x + vv.y + vv.z + vv.w;
            sq  += vv.x*vv.x + vv.y*vv.y + vv.z*vv.z + vv.w*vv.w;
        }
        #pragma unroll
        for (int o = 4; o; o >>= 1) {
            sum += __shfl_xor_sync(0xffffffffu, sum, o);
            sq  += __shfl_xor_sync(0xffffffffu, sq,  o);
        }
        if (sg == 0) {
            float m = sum * (1.f / 1024.f);
            float var = sq * (1.f / 1024.f) - m * m;
            m_s[lr] = m; r_s[lr] = rsqrtf(var + 1e-5f);
        }
    }
    __syncthreads();
    const float mm = m_s[lr], rs = r_s[lr];

    // ---- GEMM ----
    const int w = t >> 5, l = t & 31;
    const int mr  = (w >> 2) * 16;
    const int nc_ = (w & 3) * 16;
    const int g   = l >> 2, tig = l & 3;
    const int lk8 = sg * 8;

    const float* xp  = xrow + lk8;
    const float* Wp0 = W + (size_t)(c0 + lr) * 1024 + lk8;
    const float* Wp1 = W + (size_t)(c0 + 32 + lr) * 1024 + lk8;
    const float* lp  = lnw + lk8;

    float4 px0 = *(const float4*)xp,  px1 = *(const float4*)(xp + 4);
    float4 pw0 = *(const float4*)Wp0, pw1 = *(const float4*)(Wp0 + 4);
    float4 pw2 = *(const float4*)Wp1, pw3 = *(const float4*)(Wp1 + 4);

    float acc[2][4] = {{0,0,0,0},{0,0,0,0}};

    for (int k0 = 0; k0 < 1024; k0 += 64) {
        __syncthreads();
        {
            float4 pl0 = *(const float4*)(lp + k0);
            float4 pl1 = *(const float4*)(lp + k0 + 4);
            float4 a0, a1;
            a0.x = (px0.x - mm) * rs * pl0.x; a0.y = (px0.y - mm) * rs * pl0.y;
            a0.z = (px0.z - mm) * rs * pl0.z; a0.w = (px0.w - mm) * rs * pl0.w;
            a1.x = (px1.x - mm) * rs * pl1.x; a1.y = (px1.y - mm) * rs * pl1.y;
            a1.z = (px1.z - mm) * rs * pl1.z; a1.w = (px1.w - mm) * rs * pl1.w;
            *(float4*)&As[lr][lk8]     = a0;
            *(float4*)&As[lr][lk8 + 4] = a1;
            *(float4*)&Ws[lr][lk8]          = pw0; *(float4*)&Ws[lr][lk8 + 4]      = pw1;
            *(float4*)&Ws[lr + 32][lk8]     = pw2; *(float4*)&Ws[lr + 32][lk8 + 4] = pw3;
        }
        __syncthreads();
        if (k0 + 64 < 1024) {
            px0 = *(const float4*)(xp  + k0 + 64); px1 = *(const float4*)(xp  + k0 + 68);
            pw0 = *(const float4*)(Wp0 + k0 + 64); pw1 = *(const float4*)(Wp0 + k0 + 68);
            pw2 = *(const float4*)(Wp1 + k0 + 64); pw3 = *(const float4*)(Wp1 + k0 + 68);
        }
        #pragma unroll
        for (int ks = 0; ks < 8; ks++) {
            const int kb = ks * 8;
            unsigned a0 = f2tf(As[mr + g][kb + tig]);
            unsigned a1 = f2tf(As[mr + g + 8][kb + tig]);
            unsigned a2 = f2tf(As[mr + g][kb + tig + 4]);
            unsigned a3 = f2tf(As[mr + g + 8][kb + tig + 4]);
            #pragma unroll
            for (int j = 0; j < 2; j++) {
                unsigned b0 = f2tf(Ws[nc_ + j * 8 + g][kb + tig]);
                unsigned b1 = f2tf(Ws[nc_ + j * 8 + g][kb + tig + 4]);
                mma_tf32(acc[j], a0, a1, a2, a3, b0, b1);
            }
        }
    }
    const int row0 = r0 + mr + g, row1 = row0 + 8;
    #pragma unroll
    for (int j = 0; j < 2; j++) {
        const int colb = c0 + nc_ + j * 8 + 2 * tig;
        float b0v = 0.f, b1v = 0.f;
        if (bias) { b0v = bias[colb]; b1v = bias[colb + 1]; }
        OUT[(size_t)row0 * 1024 + colb]     = acc[j][0] + b0v;
        OUT[(size_t)row0 * 1024 + colb + 1] = acc[j][1] + b1v;
        OUT[(size_t)row1 * 1024 + colb]     = acc[j][2] + b0v;
        OUT[(size_t)row1 * 1024 + colb + 1] = acc[j][3] + b1v;
    }
}

// ---------------------------------------------------------------------------
// Kernel B: attention per (b,h), 128 blocks, sync-free iteration loop.
// Dynamic smem 54.2KB (qn aliases dead kt). No fill here (smem would
// throttle fill-block residency).
// ---------------------------------------------------------------------------
__global__ void __launch_bounds__(256) attn_kernel(
    const float* __restrict__ lnc, const float* __restrict__ lnd,
    const float* __restrict__ lqw, const float* __restrict__ lqb,
    const float* __restrict__ lkw, const float* __restrict__ lkb,
    const float* __restrict__ lvw, const float* __restrict__ lvb)
{
    extern __shared__ float sm[];
    const int t = threadIdx.x;
    const int aidx = blockIdx.x;
    const int b = aidx >> 4, h = aidx & 15;

    float (*w1)[65] = (float(*)[65])sm;          // wk, later wq (64x65)
    float (*w2)[65] = w1 + 64;                   // wv
    float (*kt)[65] = w2 + 64;                   // k tile; later aliased as qn
    float (*vt)[65] = kt + 16;
    float (*kn)[65] = vt + 16;
    float (*vi)[65] = kn + 16;
    float (*qc)[65] = vi + 16;
    float (*qn)[65] = kt;                        // ALIAS: kt dead after kn/vi
    float* rm  = (float*)(qc + 16);
    float* rr  = rm + 16;

    const int w = t >> 5, lane = t & 31;

    // stage wk->w1, wv->w2
    {
        const int rw = t >> 4, col = (t & 15) * 4;
        #pragma unroll
        for (int p = 0; p < 4; p++) {
            int row = p * 16 + rw;
            float4 c = *(const float4*)(lkw + row * 64 + col);
            w1[row][col] = c.x; w1[row][col+1] = c.y; w1[row][col+2] = c.z; w1[row][col+3] = c.w;
            float4 e = *(const float4*)(lvw + row * 64 + col);
            w2[row][col] = e.x; w2[row][col+1] = e.y; w2[row][col+2] = e.z; w2[row][col+3] = e.w;
        }
    }
    const int d = t & 63, s0 = t >> 6;
    const size_t base = (size_t)(b * 16) * 1024 + h * 64;
    #pragma unroll
    for (int r = 0; r < 4; r++) {
        int s = s0 + 4 * r;
        qc[s][d] = g_q[base + (size_t)s * 1024 + d];
        kt[s][d] = g_k[base + (size_t)s * 1024 + d];
        vt[s][d] = g_v[base + (size_t)s * 1024 + d];
    }
    __syncthreads();

    // kn_pre = k @ lkw.T + lkb, vi = v @ lvw.T + lvb
    {
        float akn[4], avi[4];
        const float bk = lkb[d], bv = lvb[d];
        #pragma unroll
        for (int r = 0; r < 4; r++) { akn[r] = bk; avi[r] = bv; }
        for (int e = 0; e < 64; e++) {
            float wke = w1[d][e], wve = w2[d][e];
            #pragma unroll
            for (int r = 0; r < 4; r++) {
                int s = s0 + 4 * r;
                akn[r] += kt[s][e] * wke;
                avi[r] += vt[s][e] * wve;
            }
        }
        #pragma unroll
        for (int r = 0; r < 4; r++) { int s = s0 + 4 * r; kn[s][d] = akn[r]; vi[s][d] = avi[r]; }
    }
    __syncthreads();                             // kt fully dead after this
    {   // LN over 64-dim kn rows
        const int s = t >> 4, l16 = t & 15;
        float v0 = kn[s][l16], v1 = kn[s][l16+16], v2 = kn[s][l16+32], v3 = kn[s][l16+48];
        float sum = v0+v1+v2+v3, sq = v0*v0+v1*v1+v2*v2+v3*v3;
        #pragma unroll
        for (int o = 8; o; o >>= 1) {
            sum += __shfl_xor_sync(0xffffffffu, sum, o);
            sq  += __shfl_xor_sync(0xffffffffu, sq,  o);
        }
        if (l16 == 0) {
            float m = sum * (1.f/64.f), var = sq * (1.f/64.f) - m*m;
            rm[s] = m; rr[s] = rsqrtf(var + 1e-5f);
        }
    }
    __syncthreads();
    {
        const float lndd = lnd[d];
        #pragma unroll
        for (int r = 0; r < 4; r++) {
            int s = s0 + 4 * r;
            kn[s][d] = (kn[s][d] - rm[s]) * rr[s] * lndd;
        }
    }
    __syncthreads();
    // restage wq into w1 (wk no longer needed)
    {
        const int rw = t >> 4, col = (t & 15) * 4;
        #pragma unroll
        for (int p = 0; p < 4; p++) {
            int row = p * 16 + rw;
            float4 a = *(const float4*)(lqw + row * 64 + col);
            w1[row][col] = a.x; w1[row][col+1] = a.y; w1[row][col+2] = a.z; w1[row][col+3] = a.w;
        }
    }
    __syncthreads();

    // ---- sync-free iteration loop: warp w owns rows sA=2w, sB=2w+1 ----
    const int d0 = lane, d1 = lane + 32;
    const int sA = 2 * w, sB = sA + 1;
    const float lqb0 = lqb[d0], lqb1 = lqb[d1];
    const float lnc0 = lnc[d0], lnc1 = lnc[d1];
    const size_t baseA = base + (size_t)sA * 1024;
    const size_t baseB = base + (size_t)sB * 1024;

    float diffacc = 0.f;
    float ipA0 = 0.f, ipA1 = 0.f, ipB0 = 0.f, ipB1 = 0.f;

    #pragma unroll
    for (int it = 0; it < 3; it++) {
        float aA0 = lqb0, aA1 = lqb1, aB0 = lqb0, aB1 = lqb1;
        #pragma unroll 16
        for (int e = 0; e < 64; e++) {
            float ca = qc[sA][e], cb = qc[sB][e];
            float w0 = w1[d0][e], wv1 = w1[d1][e];
            aA0 += ca * w0; aA1 += ca * wv1;
            aB0 += cb * w0; aB1 += cb * wv1;
        }
        float sumA = aA0 + aA1, sqA = aA0*aA0 + aA1*aA1;
        float sumB = aB0 + aB1, sqB = aB0*aB0 + aB1*aB1;
        #pragma unroll
        for (int o = 16; o; o >>= 1) {
            sumA += __shfl_xor_sync(0xffffffffu, sumA, o);
            sqA  += __shfl_xor_sync(0xffffffffu, sqA,  o);
            sumB += __shfl_xor_sync(0xffffffffu, sumB, o);
            sqB  += __shfl_xor_sync(0xffffffffu, sqB,  o);
        }
        float mA = sumA * (1.f/64.f), rA = rsqrtf(sqA * (1.f/64.f) - mA*mA + 1e-5f);
        float mB = sumB * (1.f/64.f), rB = rsqrtf(sqB * (1.f/64.f) - mB*mB + 1e-5f);
        qn[sA][d0] = (aA0 - mA) * rA * lnc0; qn[sA][d1] = (aA1 - mA) * rA * lnc1;
        qn[sB][d0] = (aB0 - mB) * rB * lnc0; qn[sB][d1] = (aB1 - mB) * rB * lnc1;
        __syncwarp();

        const int srow = (lane < 16) ? sA : sB;
        const int u = lane & 15;
        float lg = 0.f;
        #pragma unroll 16
        for (int e = 0; e < 64; e++) lg += qn[srow][e] * kn[u][e];
        lg *= 0.125f;
        float mx = lg;
        #pragma unroll
        for (int o = 8; o; o >>= 1) mx = fmaxf(mx, __shfl_xor_sync(0xffffffffu, mx, o));
        float ex = expf(lg - mx);
        float se = ex;
        #pragma unroll
        for (int o = 8; o; o >>= 1) se += __shfl_xor_sync(0xffffffffu, se, o);
        float p = ex / se;

        float oA0 = 0.f, oA1 = 0.f, oB0 = 0.f, oB1 = 0.f;
        #pragma unroll
        for (int uu = 0; uu < 16; uu++) {
            float pA = __shfl_sync(0xffffffffu, p, uu);
            float pB = __shfl_sync(0xffffffffu, p, uu + 16);
            float v0 = vi[uu][d0], vvv = vi[uu][d1];
            oA0 += pA * v0; oA1 += pA * vvv;
            oB0 += pB * v0; oB1 += pB * vvv;
        }

        if (it == 0) {
            ipA0 = oA0; ipA1 = oA1; ipB0 = oB0; ipB1 = oB1;
            qc[sA][d0] += oA0; qc[sA][d1] += oA1;
            qc[sB][d0] += oB0; qc[sB][d1] += oB1;
        } else if (it == 1) {
            diffacc += fabsf(oA0 - ipA0) + fabsf(oA1 - ipA1)
                     + fabsf(oB0 - ipB0) + fabsf(oB1 - ipB1);
            qc[sA][d0] += oA0; qc[sA][d1] += oA1;
            qc[sB][d0] += oB0; qc[sB][d1] += oB1;
            g_A1[baseA + d0] = oA0; g_A1[baseA + d1] = oA1;
            g_A1[baseB + d0] = oB0; g_A1[baseB + d1] = oB1;
        } else {
            g_A2[baseA + d0] = oA0; g_A2[baseA + d1] = oA1;
            g_A2[baseB + d0] = oB0; g_A2[baseB + d1] = oB1;
        }
        __syncwarp();
    }

    // block reduce diff -> g_diffpart[aidx] (consumed by proj next kernel)
    #pragma unroll
    for (int o = 16; o; o >>= 1) diffacc += __shfl_xor_sync(0xffffffffu, diffacc, o);
    __shared__ float red[8];
    if (lane == 0) red[w] = diffacc;
    __syncthreads();
    if (t == 0) {
        float v = 0.f;
        #pragma unroll
        for (int i = 0; i < 8; i++) v += red[i];
        g_diffpart[aidx] = v;
    }
}

// ---------------------------------------------------------------------------
// Kernel C: output projection (bids 0..255, split-K x4 tf32 GEMM, atomicAdd
// onto the ob-prefilled s<16 rows) + one-shot churn fill (bids 256..16639)
// covering out4[4194304, 8388608) with the active slices predicated off
// (those rows were filled by kernel A; proj atomicAdds them — disjoint).
// ---------------------------------------------------------------------------
__global__ void __launch_bounds__(256) proj_kernel(
    const float* __restrict__ ow, float* __restrict__ out,
    float4* __restrict__ out4, const float4* __restrict__ ob4)
{
    const int t = threadIdx.x;
    const int bid = blockIdx.x;

    if (bid >= 256) {
        const unsigned i = 4194304u + (unsigned)(bid - 256) * 256u + t;
        if ((i & 1048575u) >= 4096u)      // skip active s<16 slices (b4..b7)
            out4[i] = ob4[t];
        return;
    }

    const int ksl = bid >> 6;                  // k-slice 0..3
    const int sub = bid & 63;
    const int r0 = (sub >> 4) * 32;
    const int c0 = (sub & 15) * 64;
    const int kbase = ksl * 256;

    __shared__ float As[32][68];
    __shared__ float Ws[64][68];
    __shared__ float s_total;

    // deterministic diff reduction (identical order in every block)
    if (t < 32) {
        float v = 0.f;
        #pragma unroll
        for (int j = 0; j < 4; j++) v += g_diffpart[t + j * 32];
        #pragma unroll
        for (int o = 16; o; o >>= 1) v += __shfl_xor_sync(0xffffffffu, v, o);
        if (t == 0) s_total = v;
    }
    __syncthreads();
    const float diff = s_total * (1.0f / 33554432.0f);
    const float* IN = (diff < (0.01f + 0.1f * diff)) ? g_A1 : g_A2;

    const int w = t >> 5, l = t & 31;
    const int mr  = (w >> 2) * 16;
    const int nc_ = (w & 3) * 16;
    const int g   = l >> 2, tig = l & 3;
    const int lr  = t >> 3, lk8 = (t & 7) * 8;

    float acc[2][4] = {{0,0,0,0},{0,0,0,0}};

    const float* Ap  = IN + (size_t)(r0 + lr) * 1024 + kbase + lk8;
    const float* Wp0 = ow + (size_t)(c0 + lr) * 1024 + kbase + lk8;
    const float* Wp1 = ow + (size_t)(c0 + 32 + lr) * 1024 + kbase + lk8;
    float4 pa0 = *(const float4*)Ap,  pa1 = *(const float4*)(Ap + 4);
    float4 pw0 = *(const float4*)Wp0, pw1 = *(const float4*)(Wp0 + 4);
    float4 pw2 = *(const float4*)Wp1, pw3 = *(const float4*)(Wp1 + 4);

    for (int k0 = 0; k0 < 256; k0 += 64) {
        __syncthreads();
        *(float4*)&As[lr][lk8]          = pa0; *(float4*)&As[lr][lk8 + 4]      = pa1;
        *(float4*)&Ws[lr][lk8]          = pw0; *(float4*)&Ws[lr][lk8 + 4]      = pw1;
        *(float4*)&Ws[lr + 32][lk8]     = pw2; *(float4*)&Ws[lr + 32][lk8 + 4] = pw3;
        __syncthreads();
        if (k0 + 64 < 256) {
            pa0 = *(const float4*)(Ap  + k0 + 64); pa1 = *(const float4*)(Ap  + k0 + 68);
            pw0 = *(const float4*)(Wp0 + k0 + 64); pw1 = *(const float4*)(Wp0 + k0 + 68);
            pw2 = *(const float4*)(Wp1 + k0 + 64); pw3 = *(const float4*)(Wp1 + k0 + 68);
        }
        #pragma unroll
        for (int ks = 0; ks < 8; ks++) {
            const int kb = ks * 8;
            unsigned a0 = f2tf(As[mr + g][kb + tig]);
            unsigned a1 = f2tf(As[mr + g + 8][kb + tig]);
            unsigned a2 = f2tf(As[mr + g][kb + tig + 4]);
            unsigned a3 = f2tf(As[mr + g + 8][kb + tig + 4]);
            #pragma unroll
            for (int j = 0; j < 2; j++) {
                unsigned b0 = f2tf(Ws[nc_ + j * 8 + g][kb + tig]);
                unsigned b1 = f2tf(Ws[nc_ + j * 8 + g][kb + tig + 4]);
                mma_tf32(acc[j], a0, a1, a2, a3, b0, b1);
            }
        }
    }
    const int row0 = r0 + mr + g, row1 = row0 + 8;
    const size_t o0 = ((size_t)(row0 >> 4) * CTXL + (row0 & 15)) * 1024;
    const size_t o1 = ((size_t)(row1 >> 4) * CTXL + (row1 & 15)) * 1024;
    #pragma unroll
    for (int j = 0; j < 2; j++) {
        const int colb = c0 + nc_ + j * 8 + 2 * tig;
        atomicAdd(&out[o0 + colb],     acc[j][0]);
        atomicAdd(&out[o0 + colb + 1], acc[j][1]);
        atomicAdd(&out[o1 + colb],     acc[j][2]);
        atomicAdd(&out[o1 + colb + 1], acc[j][3]);
    }
}

// ---------------------------------------------------------------------------
extern "C" void kernel_launch(void* const* d_in, const int* in_sizes, int n_in,
                              void* d_out, int out_size) {
    const float* x   = (const float*)d_in[0];
    const float* qw  = (const float*)d_in[1];
    const float* qb  = (const float*)d_in[2];
    const float* kw  = (const float*)d_in[3];
    const float* vw  = (const float*)d_in[4];
    const float* vb  = (const float*)d_in[5];
    const float* ow  = (const float*)d_in[6];
    const float* ob  = (const float*)d_in[7];
    const float* lna = (const float*)d_in[8];
    const float* lnb = (const float*)d_in[9];
    const float* lnc = (const float*)d_in[10];
    const float* lnd = (const float*)d_in[11];
    const float* lqw = (const float*)d_in[12];
    const float* lqb = (const float*)d_in[13];
    const float* lkw = (const float*)d_in[14];
    const float* lkb = (const float*)d_in[15];
    const float* lvw = (const float*)d_in[16];
    const float* lvb = (const float*)d_in[17];
    float* out = (float*)d_out;

    // attn dynamic smem: (2*64*65 + 5*16*65 + 40) floats = 54240 B
    const int attn_smem = (2 * 64 * 65 + 5 * 16 * 65 + 40) * 4;
    cudaFuncSetAttribute(attn_kernel, cudaFuncAttributeMaxDynamicSharedMemorySize,
                         attn_smem);

    // A: 192 GEMM + 16384 fill ([0, 4194304)) + 64 fill (b4..b7 active slices)
    qkv_kernel<<<16640, 256>>>(x, qw, qb, kw, vw, vb, lna, lnb,
                               (float4*)out, (const float4*)ob);
    // B: attention only
    attn_kernel<<<128, 256, attn_smem>>>(lnc, lnd, lqw, lqb, lkw, lkb, lvw, lvb);
    // C: 256 proj + 16384 fill ([4194304, 8388608) minus active slices)
    proj_kernel<<<16640, 256>>>(ow, out, (float4*)out, (const float4*)ob);
}